// round 16
// baseline (speedup 1.0000x reference)
#include <cuda_runtime.h>
#include <cuda_fp16.h>
#include <cstdint>

// Problem constants
#define BB 4
#define SS 2048
#define DD 1024
#define HH 16
#define DKK 64
#define MM (BB*SS)            // 8192
#define OUT_PLANE (BB*SS*DD)  // 8388608
#define HPLANE (BB*HH*SS*DKK) // 8388608

// Q pre-scale: (1/sqrt(64)) * log2(e)  -> softmax runs in exp2 domain
#define QSCALE 0.18033688011112042f

// Scratch (allocation-free rule: __device__ globals), all fp16 fragment layouts
__device__ __half g_Qh[HPLANE];        // Q proj, A-frag quads, *QSCALE
__device__ __half g_rKh[HPLANE];       // K proj, B-frag pairs (GEMM1)
__device__ __half g_rVh[HPLANE];       // V proj, B-frag pairs (GEMM2)
__device__ __half g_ctx[BB*SS*DD];     // attention context, A-frag quads
__device__ __half g_rw[4*DD*DD];       // weights, B-frag pairs
__device__ __half g_pA[3*(size_t)MM*DD]; // q,k,v inputs, A-frag quads

// fp16 m16n8k16 fragment layouts, g=lane>>2, t=lane&3:
//  A quad (jm=m/16, jk16=k/16, lane): uint4 idx = (jm*NJK16 + jk16)*32 + lane
//  B pair (jn=n/8, jk16, lane): uint2 idx = (jn*NJK16 + jk16)*32 + lane

// ---------------------------------------------------------------------------
// helpers
// ---------------------------------------------------------------------------
__device__ __forceinline__ uint32_t f2h2(float lo, float hi) {
    __half2 h = __floats2half2_rn(lo, hi);
    return *reinterpret_cast<uint32_t*>(&h);
}

__device__ __forceinline__ float ex2(float x) {
    float r;
    asm("ex2.approx.f32 %0, %1;" : "=f"(r) : "f"(x));
    return r;
}

// D += A(16x16) * B(16x8), fp16 inputs, fp32 accum
__device__ __forceinline__ void mma16(float* c, uint32_t a0, uint32_t a1,
                                      uint32_t a2, uint32_t a3,
                                      uint32_t b0, uint32_t b1) {
    asm volatile(
        "mma.sync.aligned.m16n8k16.row.col.f32.f16.f16.f32 "
        "{%0,%1,%2,%3}, {%4,%5,%6,%7}, {%8,%9}, {%0,%1,%2,%3};\n"
        : "+f"(c[0]), "+f"(c[1]), "+f"(c[2]), "+f"(c[3])
        : "r"(a0), "r"(a1), "r"(a2), "r"(a3), "r"(b0), "r"(b1));
}

__device__ __forceinline__ uint32_t smem_u32(const void* p) {
    uint32_t a;
    asm("{ .reg .u64 t; cvta.to.shared.u64 t, %1; cvt.u32.u64 %0, t; }"
        : "=r"(a) : "l"(p));
    return a;
}

__device__ __forceinline__ void cp16(uint32_t saddr, const void* gptr) {
    asm volatile("cp.async.cg.shared.global [%0], [%1], 16;"
                 :: "r"(saddr), "l"(gptr));
}
#define CP_COMMIT() asm volatile("cp.async.commit_group;" ::: "memory")
#define CP_WAIT(n)  asm volatile("cp.async.wait_group %0;" :: "n"(n) : "memory")

// ---------------------------------------------------------------------------
// fused prologue: weight permute (blocks 0..511) + input permute (512..3583)
// ---------------------------------------------------------------------------
__global__ __launch_bounds__(256) void prep_k(const float* __restrict__ q,
                                              const float* __restrict__ k,
                                              const float* __restrict__ v,
                                              const float* __restrict__ wq,
                                              const float* __restrict__ wk,
                                              const float* __restrict__ wv,
                                              const float* __restrict__ wo)
{
    __shared__ float S[64 * 132];
    const int b = blockIdx.x;
    const int t = threadIdx.x;

    if (b < 512) {
        const int jnT = b & 15;
        const int jkT = (b >> 4) & 7;
        const int z   = b >> 7;
        const float* src = (z == 0) ? wq : (z == 1) ? wk : (z == 2) ? wv : wo;
        uint2* dst = (uint2*)(g_rw + (size_t)z * DD * DD);
#pragma unroll
        for (int i = 0; i < 8; i++) {
            int f = i * 256 + t;
            int r = f >> 5, c4 = f & 31;
            float4 vv = *(const float4*)(src + (size_t)(jnT * 64 + r) * DD
                                             + jkT * 128 + c4 * 4);
            *(float4*)&S[r * 132 + c4 * 4] = vv;
        }
        __syncthreads();
#pragma unroll
        for (int i = 0; i < 8; i++) {
            int f = i * 256 + t;
            int ln = f & 31, qq = f >> 5;
            int jk_l = qq & 7, jn_l = qq >> 3;
            int g2 = ln >> 2, t2 = ln & 3;
            int r = jn_l * 8 + g2, c = jk_l * 16 + 2 * t2;
            uint2 o;
            o.x = f2h2(S[r * 132 + c],     S[r * 132 + c + 1]);
            o.y = f2h2(S[r * 132 + c + 8], S[r * 132 + c + 9]);
            size_t idx = ((size_t)(jnT * 8 + jn_l) * 64 + jkT * 8 + jk_l) * 32 + ln;
            dst[idx] = o;
        }
    } else {
        const int idx0 = b - 512;
        const int jm = idx0 & 511;
        const int ch = (idx0 >> 9) & 1;
        const int z  = idx0 >> 10;
        const float* src = (z == 0) ? q : (z == 1) ? k : v;
        uint4* dst = (uint4*)(g_pA + (size_t)z * MM * DD);
#pragma unroll
        for (int i = 0; i < 8; i++) {
            int f = i * 256 + t;
            int r = f >> 7, c4 = f & 127;
            float4 vv = *(const float4*)(src + (size_t)(jm * 16 + r) * DD
                                             + ch * 512 + c4 * 4);
            *(float4*)&S[r * 516 + c4 * 4] = vv;
        }
        __syncthreads();
#pragma unroll
        for (int i = 0; i < 4; i++) {
            int f = i * 256 + t;
            int ln = f & 31, jk_l = f >> 5;
            int g = ln >> 2, t2 = ln & 3;
            int c = jk_l * 16 + 2 * t2;
            uint4 o;
            o.x = f2h2(S[g * 516 + c],           S[g * 516 + c + 1]);
            o.y = f2h2(S[(g + 8) * 516 + c],     S[(g + 8) * 516 + c + 1]);
            o.z = f2h2(S[g * 516 + c + 8],       S[g * 516 + c + 9]);
            o.w = f2h2(S[(g + 8) * 516 + c + 8], S[(g + 8) * 516 + c + 9]);
            size_t di = ((size_t)jm * 64 + ch * 32 + jk_l) * 32 + ln;
            dst[di] = o;
        }
    }
}

// ---------------------------------------------------------------------------
// FP16 GEMM, BK=64 (4 k16), 3-stage cp.async ring (32KB stages).
// Block tile 128x128, 256 thr = 8 warps (4M x 2N), warp = 32x64. 16 chunks.
// MODE: 0 flat fp32; 1 Q frags (*QSCALE); 2 K (fp32 out + K-frags);
//       3 V (fp32 out + V-frags).
// ---------------------------------------------------------------------------
#define GEMM_SMEM 98304

template<int MODE>
__device__ __forceinline__ void gemm_body(const __half* __restrict__ A2h,
                                          const __half* __restrict__ W2h,
                                          float* __restrict__ out_full)
{
    extern __shared__ float dsm[];
    const uint32_t sA = smem_u32(dsm);            // 3 x 16KB A stages
    const uint32_t sB = sA + 3 * 16384;           // 3 x 16KB B stages

    const int tid  = threadIdx.x;
    const int lane = tid & 31;
    const int w    = tid >> 5;
    const int g    = lane >> 2;
    const int tg   = lane & 3;
    const int wm   = w & 3;
    const int wn   = w >> 2;

    const int m0  = blockIdx.y << 7;
    const int n0  = blockIdx.x << 7;
    const int jm0 = blockIdx.y * 8;
    const int jn0 = blockIdx.x * 16;

    const int ajm = tid >> 5, ati = tid & 31;
    const uint4* Ag = (const uint4*)A2h + (size_t)(jm0 + ajm) * 2048;
    const uint2* Bg2 = (const uint2*)W2h;

#pragma unroll
    for (int c = 0; c < 3; c++) {
#pragma unroll
        for (int i = 0; i < 4; i++) {
            cp16(sA + (uint32_t)(c * 16384 + ((ajm * 4 + i) * 32 + ati) * 16),
                 Ag + (c * 4 + i) * 32 + ati);
            int f = tid + i * 256;
            int jn_l = f >> 6, rem = f & 63;
            int jkl = rem >> 4, lp = rem & 15;
            cp16(sB + (uint32_t)(c * 16384 + ((jn_l * 4 + jkl) * 32 + lp * 2) * 8),
                 Bg2 + (size_t)(jn0 + jn_l) * 2048 + (c * 4 + jkl) * 32 + lp * 2);
        }
        CP_COMMIT();
    }

    float acc[2][8][4];
#pragma unroll
    for (int mf = 0; mf < 2; mf++)
#pragma unroll
        for (int nf = 0; nf < 8; nf++)
#pragma unroll
            for (int r = 0; r < 4; r++) acc[mf][nf][r] = 0.0f;

    for (int t = 0; t < 16; t++) {
        if (t < 15) { CP_WAIT(1); } else { CP_WAIT(0); }
        __syncthreads();
        if (t + 2 < 16) {
            int st = (t + 2) % 3;
#pragma unroll
            for (int i = 0; i < 4; i++) {
                cp16(sA + (uint32_t)(st * 16384 + ((ajm * 4 + i) * 32 + ati) * 16),
                     Ag + ((t + 2) * 4 + i) * 32 + ati);
                int f = tid + i * 256;
                int jn_l = f >> 6, rem = f & 63;
                int jkl = rem >> 4, lp = rem & 15;
                cp16(sB + (uint32_t)(st * 16384 + ((jn_l * 4 + jkl) * 32 + lp * 2) * 8),
                     Bg2 + (size_t)(jn0 + jn_l) * 2048 + ((t + 2) * 4 + jkl) * 32 + lp * 2);
            }
            CP_COMMIT();
        }
        const int st = t % 3;
        const uint4* as4 = (const uint4*)((const char*)dsm + st * 16384);
        const uint2* bs2 = (const uint2*)((const char*)dsm + 3 * 16384 + st * 16384);
#pragma unroll
        for (int ks = 0; ks < 4; ks++) {
            uint4 a0 = as4[((wm * 2 + 0) * 4 + ks) * 32 + lane];
            uint4 a1 = as4[((wm * 2 + 1) * 4 + ks) * 32 + lane];
#pragma unroll
            for (int nf = 0; nf < 8; nf++) {
                uint2 b = bs2[((wn * 8 + nf) * 4 + ks) * 32 + lane];
                mma16(acc[0][nf], a0.x, a0.y, a0.z, a0.w, b.x, b.y);
                mma16(acc[1][nf], a1.x, a1.y, a1.z, a1.w, b.x, b.y);
            }
        }
    }

    if (MODE == 0) {
#pragma unroll
        for (int mf = 0; mf < 2; mf++) {
#pragma unroll
            for (int half = 0; half < 2; half++) {
                int m = m0 + (wm << 5) + (mf << 4) + g + half * 8;
#pragma unroll
                for (int nf = 0; nf < 8; nf++) {
                    int e = n0 + (wn << 6) + (nf << 3) + (tg << 1);
                    float2 val;
                    val.x = acc[mf][nf][half * 2 + 0];
                    val.y = acc[mf][nf][half * 2 + 1];
                    *(float2*)&out_full[(size_t)m * DD + e] = val;
                }
            }
        }
        return;
    }

    // staged epilogue: C tile -> smem fp32 [128][132]
    __syncthreads();
    float* stage = dsm;
#pragma unroll
    for (int mf = 0; mf < 2; mf++) {
#pragma unroll
        for (int half = 0; half < 2; half++) {
            int r = (wm << 5) + (mf << 4) + (half << 3) + g;
#pragma unroll
            for (int nf = 0; nf < 8; nf++) {
                int c = (wn << 6) + (nf << 3) + (tg << 1);
                float2 val;
                val.x = acc[mf][nf][half * 2 + 0];
                val.y = acc[mf][nf][half * 2 + 1];
                *(float2*)&stage[r * 132 + c] = val;
            }
        }
    }
    __syncthreads();

    const int bq = m0 >> 11;
    const int h0 = n0 >> 6;

    if (MODE == 2 || MODE == 3) {
#pragma unroll
        for (int i = 0; i < 16; i++) {
            int f = i * 256 + tid;
            int row = f >> 5, c4 = f & 31;
            float4 v = *(const float4*)&stage[row * 132 + c4 * 4];
            int m = m0 + row;
            int s = m & 2047;
            int e = n0 + c4 * 4;
            int h = e >> 6, dk = e & 63;
            *(float4*)&out_full[((((size_t)bq * HH + h) << 11) + s) * DKK + dk] = v;
        }
    }

    if (MODE == 1) {
        const int jmb = (m0 & 2047) >> 4;
        uint4* dst = (uint4*)g_Qh;
#pragma unroll
        for (int i = 0; i < 8; i++) {
            int f = i * 256 + tid;
            int ln = f & 31, qq = f >> 5;
            int jk = qq & 3, jm_l = (qq >> 2) & 7, hs = (qq >> 5) & 1;
            int g2 = ln >> 2, t2 = ln & 3;
            int r = jm_l * 16 + g2, c = hs * 64 + jk * 16 + 2 * t2;
            uint4 o;
            o.x = f2h2(stage[r * 132 + c] * QSCALE,       stage[r * 132 + c + 1] * QSCALE);
            o.y = f2h2(stage[(r + 8) * 132 + c] * QSCALE, stage[(r + 8) * 132 + c + 1] * QSCALE);
            o.z = f2h2(stage[r * 132 + c + 8] * QSCALE,   stage[r * 132 + c + 9] * QSCALE);
            o.w = f2h2(stage[(r + 8) * 132 + c + 8] * QSCALE,
                       stage[(r + 8) * 132 + c + 9] * QSCALE);
            size_t idx = (((size_t)(bq * HH + h0 + hs) * 128 + jmb + jm_l) * 4 + jk) * 32 + ln;
            dst[idx] = o;
        }
    } else if (MODE == 2) {
        const int kt0 = (m0 & 2047) >> 6;
        uint2* dst = (uint2*)g_rKh;
#pragma unroll
        for (int i = 0; i < 16; i++) {
            int f = i * 256 + tid;
            int ln = f & 31, qq = f >> 5;
            int jk = qq & 3, jn = (qq >> 2) & 7, ktl = (qq >> 5) & 1, hs = qq >> 6;
            int g2 = ln >> 2, t2 = ln & 3;
            int r = ktl * 64 + jn * 8 + g2;
            int c = hs * 64 + jk * 16 + 2 * t2;
            uint2 o;
            o.x = f2h2(stage[r * 132 + c],     stage[r * 132 + c + 1]);
            o.y = f2h2(stage[r * 132 + c + 8], stage[r * 132 + c + 9]);
            size_t idx = ((size_t)(bq * HH + h0 + hs) * 32 + kt0 + ktl) * 1024
                       + (jn * 4 + jk) * 32 + ln;
            dst[idx] = o;
        }
    } else if (MODE == 3) {
        const int kt0 = (m0 & 2047) >> 6;
        uint2* dst = (uint2*)g_rVh;
#pragma unroll
        for (int i = 0; i < 16; i++) {
            int f = i * 256 + tid;
            int ln = f & 31, qq = f >> 5;
            int jk = qq & 3, jn = (qq >> 2) & 7, ktl = (qq >> 5) & 1, hs = qq >> 6;
            int g2 = ln >> 2, t2 = ln & 3;
            int r = ktl * 64 + jk * 16 + 2 * t2;
            int c = hs * 64 + jn * 8 + g2;
            uint2 o;
            o.x = f2h2(stage[r * 132 + c],       stage[(r + 1) * 132 + c]);
            o.y = f2h2(stage[(r + 8) * 132 + c], stage[(r + 9) * 132 + c]);
            size_t idx = ((size_t)(bq * HH + h0 + hs) * 32 + kt0 + ktl) * 1024
                       + (jn * 4 + jk) * 32 + ln;
            dst[idx] = o;
        }
    }
}

__global__ __launch_bounds__(256, 2) void gemm_qkv(
    float* __restrict__ keyh, float* __restrict__ valh)
{
    const int z = blockIdx.z;
    const __half* A2 = g_pA + (size_t)z * MM * DD;
    const __half* W2 = g_rw + (size_t)z * DD * DD;
    if (z == 0)      gemm_body<1>(A2, W2, nullptr);
    else if (z == 1) gemm_body<2>(A2, W2, keyh);
    else             gemm_body<3>(A2, W2, valh);
}

__global__ __launch_bounds__(256, 2) void gemm_out_k(float* __restrict__ O)
{
    gemm_body<0>(g_ctx, g_rw + (size_t)3 * DD * DD, O);
}

// ---------------------------------------------------------------------------
// FP16 causal flash attention, exp2-domain softmax, 4-slot K/V ring,
// two 64-key tiles per loop iteration. Block: 256 thr (8 warps), 256 queries;
// each K/V tile staged once serves 8 warps (2x the prior reuse).
// Grid: (S/256, B*H). 1 block/SM (regs). smem: 4x8KB K + 4x8KB V = 64KB.
// ---------------------------------------------------------------------------
#define ATT_SMEM (8 * 8192)

__global__ __launch_bounds__(256, 1) void attn_tc()
{
    extern __shared__ float sm[];
    const uint32_t uKb = smem_u32(sm);          // 4 x 8KB K
    const uint32_t uVb = uKb + 4 * 8192;        // 4 x 8KB V

    const int tid  = threadIdx.x;
    const int lane = tid & 31;
    const int w    = tid >> 5;          // 0..7
    const int g    = lane >> 2;
    const int tg   = lane & 3;
    const int wrow = w << 5;            // 0..224
    const int bxr  = gridDim.x - 1 - blockIdx.x;   // heavy blocks first
    const int bh   = blockIdx.y;

    const int qwarp = bxr * 256 + wrow;

    const __half* Ktiles = g_rKh + (size_t)bh * 32 * 4096;
    const __half* Vtiles = g_rVh + (size_t)bh * 32 * 4096;
    const int ktmax = 4 * bxr + 3;   // odd -> tiles form exact pairs

    // prologue: prefetch tiles 0 and 1 into ring slots 0 and 1 (256 threads)
#pragma unroll
    for (int c = 0; c < 2; c++) {
#pragma unroll
        for (int u = 0; u < 2; u++) {
            int f = u * 256 + tid;
            cp16(uKb + (uint32_t)(c * 8192 + f * 16), Ktiles + (size_t)c * 4096 + f * 8);
            cp16(uVb + (uint32_t)(c * 8192 + f * 16), Vtiles + (size_t)c * 4096 + f * 8);
        }
        CP_COMMIT();
    }

    // Q a-fragments straight from global (pre-scaled by QSCALE, fp16)
    uint4 aQ[2][4];
#pragma unroll
    for (int mf = 0; mf < 2; mf++) {
        const uint4* Qf = (const uint4*)g_Qh
                        + ((size_t)bh * 128 + bxr * 16 + w * 2 + mf) * 128;
#pragma unroll
        for (int jk = 0; jk < 4; jk++)
            aQ[mf][jk] = Qf[jk * 32 + lane];
    }

    float accO[2][8][4];
#pragma unroll
    for (int mf = 0; mf < 2; mf++)
#pragma unroll
        for (int nf = 0; nf < 8; nf++)
#pragma unroll
            for (int r = 0; r < 4; r++) accO[mf][nf][r] = 0.0f;
    float m_[2][2] = {{-1e30f, -1e30f}, {-1e30f, -1e30f}};
    float l_[2][2] = {{0.0f, 0.0f}, {0.0f, 0.0f}};

    for (int ktt = 0; ktt <= ktmax; ktt += 2) {
        CP_WAIT(0);        // tiles ktt, ktt+1 resident
        __syncthreads();   // ... and every warp done with slots of ktt-2,ktt-1

        // prefetch next pair into slots (ktt+2)&3, (ktt+3)&3
#pragma unroll
        for (int d = 2; d < 4; d++) {
            int tt = ktt + d;
            if (tt <= ktmax) {
                const int bsel = tt & 3;
                const __half* Kn = Ktiles + (size_t)tt * 4096;
                const __half* Vn = Vtiles + (size_t)tt * 4096;
#pragma unroll
                for (int u = 0; u < 2; u++) {
                    int f = u * 256 + tid;
                    cp16(uKb + (uint32_t)(bsel * 8192 + f * 16), Kn + f * 8);
                    cp16(uVb + (uint32_t)(bsel * 8192 + f * 16), Vn + f * 8);
                }
                CP_COMMIT();
            }
        }

#pragma unroll
        for (int sub = 0; sub < 2; sub++) {
            const int kt = ktt + sub;
            const uint2* Kc = (const uint2*)((const char*)sm + (kt & 3) * 8192);
            const uint2* Vc = (const uint2*)((const char*)sm + 4 * 8192 + (kt & 3) * 8192);

            const bool skip = (kt * 64) > (qwarp + 31);
            if (skip) continue;

            float sacc[2][8][4];
#pragma unroll
            for (int mf = 0; mf < 2; mf++)
#pragma unroll
                for (int nf = 0; nf < 8; nf++)
#pragma unroll
                    for (int r = 0; r < 4; r++) sacc[mf][nf][r] = 0.0f;

            // GEMM1: S2 = (Q*log2e/8) @ K^T
#pragma unroll
            for (int jk = 0; jk < 4; jk++) {
#pragma unroll
                for (int nf = 0; nf < 8; nf++) {
                    uint2 b = Kc[(nf * 4 + jk) * 32 + lane];
                    mma16(sacc[0][nf], aQ[0][jk].x, aQ[0][jk].y, aQ[0][jk].z,
                          aQ[0][jk].w, b.x, b.y);
                    mma16(sacc[1][nf], aQ[1][jk].x, aQ[1][jk].y, aQ[1][jk].z,
                          aQ[1][jk].w, b.x, b.y);
                }
            }

            // causal mask (absolute indices)
            if (kt * 64 + 63 > qwarp) {
                int koff = kt * 64;
#pragma unroll
                for (int mf = 0; mf < 2; mf++) {
                    int r0 = qwarp + (mf << 4) + g, r1 = r0 + 8;
#pragma unroll
                    for (int nf = 0; nf < 8; nf++) {
                        int c0 = koff + nf * 8 + tg * 2, c1 = c0 + 1;
                        if (c0 > r0) sacc[mf][nf][0] = -1e30f;
                        if (c1 > r0) sacc[mf][nf][1] = -1e30f;
                        if (c0 > r1) sacc[mf][nf][2] = -1e30f;
                        if (c1 > r1) sacc[mf][nf][3] = -1e30f;
                    }
                }
            }

            // online softmax in exp2 domain per (mf, row-half)
#pragma unroll
            for (int mf = 0; mf < 2; mf++) {
                float rm0 = -1e30f, rm1 = -1e30f;
#pragma unroll
                for (int nf = 0; nf < 8; nf++) {
                    rm0 = fmaxf(rm0, fmaxf(sacc[mf][nf][0], sacc[mf][nf][1]));
                    rm1 = fmaxf(rm1, fmaxf(sacc[mf][nf][2], sacc[mf][nf][3]));
                }
                rm0 = fmaxf(rm0, __shfl_xor_sync(0xFFFFFFFFu, rm0, 1));
                rm0 = fmaxf(rm0, __shfl_xor_sync(0xFFFFFFFFu, rm0, 2));
                rm1 = fmaxf(rm1, __shfl_xor_sync(0xFFFFFFFFu, rm1, 1));
                rm1 = fmaxf(rm1, __shfl_xor_sync(0xFFFFFFFFu, rm1, 2));
                float mn0 = fmaxf(m_[mf][0], rm0), mn1 = fmaxf(m_[mf][1], rm1);
                float al0 = ex2(m_[mf][0] - mn0), al1 = ex2(m_[mf][1] - mn1);
                float rs0 = 0.0f, rs1 = 0.0f;
#pragma unroll
                for (int nf = 0; nf < 8; nf++) {
                    sacc[mf][nf][0] = ex2(sacc[mf][nf][0] - mn0);
                    sacc[mf][nf][1] = ex2(sacc[mf][nf][1] - mn0);
                    sacc[mf][nf][2] = ex2(sacc[mf][nf][2] - mn1);
                    sacc[mf][nf][3] = ex2(sacc[mf][nf][3] - mn1);
                    rs0 += sacc[mf][nf][0] + sacc[mf][nf][1];
                    rs1 += sacc[mf][nf][2] + sacc[mf][nf][3];
                }
                rs0 += __shfl_xor_sync(0xFFFFFFFFu, rs0, 1);
                rs0 += __shfl_xor_sync(0xFFFFFFFFu, rs0, 2);
                rs1 += __shfl_xor_sync(0xFFFFFFFFu, rs1, 1);
                rs1 += __shfl_xor_sync(0xFFFFFFFFu, rs1, 2);
                l_[mf][0] = l_[mf][0] * al0 + rs0;
                l_[mf][1] = l_[mf][1] * al1 + rs1;
                m_[mf][0] = mn0; m_[mf][1] = mn1;
#pragma unroll
                for (int nf = 0; nf < 8; nf++) {
                    accO[mf][nf][0] *= al0; accO[mf][nf][1] *= al0;
                    accO[mf][nf][2] *= al1; accO[mf][nf][3] *= al1;
                }
            }

            // GEMM2: O += P @ V (register-local P repack)
#pragma unroll
            for (int jk = 0; jk < 4; jk++) {
                uint32_t pa[2][4];
#pragma unroll
                for (int mf = 0; mf < 2; mf++) {
                    pa[mf][0] = f2h2(sacc[mf][2*jk  ][0], sacc[mf][2*jk  ][1]);
                    pa[mf][1] = f2h2(sacc[mf][2*jk  ][2], sacc[mf][2*jk  ][3]);
                    pa[mf][2] = f2h2(sacc[mf][2*jk+1][0], sacc[mf][2*jk+1][1]);
                    pa[mf][3] = f2h2(sacc[mf][2*jk+1][2], sacc[mf][2*jk+1][3]);
                }
#pragma unroll
                for (int nf = 0; nf < 8; nf++) {
                    uint2 b = Vc[(nf * 4 + jk) * 32 + lane];
                    mma16(accO[0][nf], pa[0][0], pa[0][1], pa[0][2], pa[0][3],
                          b.x, b.y);
                    mma16(accO[1][nf], pa[1][0], pa[1][1], pa[1][2], pa[1][3],
                          b.x, b.y);
                }
            }
        }
    }

    // epilogue: normalize, register-local repack to A-frag quads, direct STG
    {
        const int b = bh >> 4;
        const int h = bh & 15;
        uint4* ctx4 = (uint4*)g_ctx;
#pragma unroll
        for (int mf = 0; mf < 2; mf++) {
            float inv0 = 1.0f / l_[mf][0], inv1 = 1.0f / l_[mf][1];
            size_t jm = (size_t)b * 128 + bxr * 16 + w * 2 + mf;
#pragma unroll
            for (int jk = 0; jk < 4; jk++) {
                uint4 o;
                o.x = f2h2(accO[mf][2*jk  ][0] * inv0, accO[mf][2*jk  ][1] * inv0);
                o.y = f2h2(accO[mf][2*jk  ][2] * inv1, accO[mf][2*jk  ][3] * inv1);
                o.z = f2h2(accO[mf][2*jk+1][0] * inv0, accO[mf][2*jk+1][1] * inv0);
                o.w = f2h2(accO[mf][2*jk+1][2] * inv1, accO[mf][2*jk+1][3] * inv1);
                ctx4[(jm * 64 + h * 4 + jk) * 32 + lane] = o;
            }
        }
    }
}

// ---------------------------------------------------------------------------
extern "C" void kernel_launch(void* const* d_in, const int* in_sizes, int n_in,
                              void* d_out, int out_size)
{
    const float* q   = (const float*)d_in[0];
    const float* k   = (const float*)d_in[1];
    const float* v   = (const float*)d_in[2];
    // d_in[3] = mask (causal tril) — computed analytically in-kernel
    const float* w_q = (const float*)d_in[4];
    const float* w_k = (const float*)d_in[5];
    const float* w_v = (const float*)d_in[6];
    const float* w_o = (const float*)d_in[7];

    float* out  = (float*)d_out;
    float* keyh = out + OUT_PLANE;
    float* valh = out + 2 * (size_t)OUT_PLANE;

    static bool configured = false;
    if (!configured) {
        cudaFuncSetAttribute(gemm_qkv, cudaFuncAttributeMaxDynamicSharedMemorySize,
                             GEMM_SMEM);
        cudaFuncSetAttribute(gemm_out_k, cudaFuncAttributeMaxDynamicSharedMemorySize,
                             GEMM_SMEM);
        cudaFuncSetAttribute(attn_tc, cudaFuncAttributeMaxDynamicSharedMemorySize,
                             ATT_SMEM);
        configured = true;
    }

    prep_k<<<3584, 256>>>(q, k, v, w_q, w_k, w_v, w_o);

    dim3 qkvgrid(DD / 128, MM / 128, 3);   // (8, 64, 3)
    gemm_qkv<<<qkvgrid, 256, GEMM_SMEM>>>(keyh, valh);

    dim3 agrid(SS / 256, BB * HH);         // (8, 64)
    attn_tc<<<agrid, 256, ATT_SMEM>>>();

    dim3 ogrid(DD / 128, MM / 128, 1);     // (8, 64)
    gemm_out_k<<<ogrid, 256, GEMM_SMEM>>>(out);
}

// round 17
// speedup vs baseline: 1.0351x; 1.0351x over previous
#include <cuda_runtime.h>
#include <cuda_fp16.h>
#include <cstdint>

// Problem constants
#define BB 4
#define SS 2048
#define DD 1024
#define HH 16
#define DKK 64
#define MM (BB*SS)            // 8192
#define OUT_PLANE (BB*SS*DD)  // 8388608
#define HPLANE (BB*HH*SS*DKK) // 8388608

// Q pre-scale: (1/sqrt(64)) * log2(e)  -> softmax runs in exp2 domain
#define QSCALE 0.18033688011112042f

// Scratch (allocation-free rule: __device__ globals), all fp16 fragment layouts
__device__ __half g_Qh[HPLANE];        // Q proj, A-frag quads, *QSCALE
__device__ __half g_rKh[HPLANE];       // K proj, B-frag pairs (GEMM1)
__device__ __half g_rVh[HPLANE];       // V proj, B-frag pairs (GEMM2)
__device__ __half g_ctx[BB*SS*DD];     // attention context, A-frag quads
__device__ __half g_rw[4*DD*DD];       // weights, B-frag pairs
__device__ __half g_pA[3*(size_t)MM*DD]; // q,k,v inputs, A-frag quads

// fp16 m16n8k16 fragment layouts, g=lane>>2, t=lane&3:
//  A quad (jm=m/16, jk16=k/16, lane): uint4 idx = (jm*NJK16 + jk16)*32 + lane
//  B pair (jn=n/8, jk16, lane): uint2 idx = (jn*NJK16 + jk16)*32 + lane

// ---------------------------------------------------------------------------
// helpers
// ---------------------------------------------------------------------------
__device__ __forceinline__ uint32_t f2h2(float lo, float hi) {
    __half2 h = __floats2half2_rn(lo, hi);
    return *reinterpret_cast<uint32_t*>(&h);
}

__device__ __forceinline__ float ex2(float x) {
    float r;
    asm("ex2.approx.f32 %0, %1;" : "=f"(r) : "f"(x));
    return r;
}

// D += A(16x16) * B(16x8), fp16 inputs, fp32 accum
__device__ __forceinline__ void mma16(float* c, uint32_t a0, uint32_t a1,
                                      uint32_t a2, uint32_t a3,
                                      uint32_t b0, uint32_t b1) {
    asm volatile(
        "mma.sync.aligned.m16n8k16.row.col.f32.f16.f16.f32 "
        "{%0,%1,%2,%3}, {%4,%5,%6,%7}, {%8,%9}, {%0,%1,%2,%3};\n"
        : "+f"(c[0]), "+f"(c[1]), "+f"(c[2]), "+f"(c[3])
        : "r"(a0), "r"(a1), "r"(a2), "r"(a3), "r"(b0), "r"(b1));
}

__device__ __forceinline__ uint32_t smem_u32(const void* p) {
    uint32_t a;
    asm("{ .reg .u64 t; cvta.to.shared.u64 t, %1; cvt.u32.u64 %0, t; }"
        : "=r"(a) : "l"(p));
    return a;
}

__device__ __forceinline__ void cp16(uint32_t saddr, const void* gptr) {
    asm volatile("cp.async.cg.shared.global [%0], [%1], 16;"
                 :: "r"(saddr), "l"(gptr));
}
#define CP_COMMIT() asm volatile("cp.async.commit_group;" ::: "memory")
#define CP_WAIT(n)  asm volatile("cp.async.wait_group %0;" :: "n"(n) : "memory")

// ---------------------------------------------------------------------------
// fused prologue: weight permute (blocks 0..511) + input permute (512..3583)
// ---------------------------------------------------------------------------
__global__ __launch_bounds__(256) void prep_k(const float* __restrict__ q,
                                              const float* __restrict__ k,
                                              const float* __restrict__ v,
                                              const float* __restrict__ wq,
                                              const float* __restrict__ wk,
                                              const float* __restrict__ wv,
                                              const float* __restrict__ wo)
{
    __shared__ float S[64 * 132];
    const int b = blockIdx.x;
    const int t = threadIdx.x;

    if (b < 512) {
        const int jnT = b & 15;
        const int jkT = (b >> 4) & 7;
        const int z   = b >> 7;
        const float* src = (z == 0) ? wq : (z == 1) ? wk : (z == 2) ? wv : wo;
        uint2* dst = (uint2*)(g_rw + (size_t)z * DD * DD);
#pragma unroll
        for (int i = 0; i < 8; i++) {
            int f = i * 256 + t;
            int r = f >> 5, c4 = f & 31;
            float4 vv = *(const float4*)(src + (size_t)(jnT * 64 + r) * DD
                                             + jkT * 128 + c4 * 4);
            *(float4*)&S[r * 132 + c4 * 4] = vv;
        }
        __syncthreads();
#pragma unroll
        for (int i = 0; i < 8; i++) {
            int f = i * 256 + t;
            int ln = f & 31, qq = f >> 5;
            int jk_l = qq & 7, jn_l = qq >> 3;
            int g2 = ln >> 2, t2 = ln & 3;
            int r = jn_l * 8 + g2, c = jk_l * 16 + 2 * t2;
            uint2 o;
            o.x = f2h2(S[r * 132 + c],     S[r * 132 + c + 1]);
            o.y = f2h2(S[r * 132 + c + 8], S[r * 132 + c + 9]);
            size_t idx = ((size_t)(jnT * 8 + jn_l) * 64 + jkT * 8 + jk_l) * 32 + ln;
            dst[idx] = o;
        }
    } else {
        const int idx0 = b - 512;
        const int jm = idx0 & 511;
        const int ch = (idx0 >> 9) & 1;
        const int z  = idx0 >> 10;
        const float* src = (z == 0) ? q : (z == 1) ? k : v;
        uint4* dst = (uint4*)(g_pA + (size_t)z * MM * DD);
#pragma unroll
        for (int i = 0; i < 8; i++) {
            int f = i * 256 + t;
            int r = f >> 7, c4 = f & 127;
            float4 vv = *(const float4*)(src + (size_t)(jm * 16 + r) * DD
                                             + ch * 512 + c4 * 4);
            *(float4*)&S[r * 516 + c4 * 4] = vv;
        }
        __syncthreads();
#pragma unroll
        for (int i = 0; i < 4; i++) {
            int f = i * 256 + t;
            int ln = f & 31, jk_l = f >> 5;
            int g = ln >> 2, t2 = ln & 3;
            int c = jk_l * 16 + 2 * t2;
            uint4 o;
            o.x = f2h2(S[g * 516 + c],           S[g * 516 + c + 1]);
            o.y = f2h2(S[(g + 8) * 516 + c],     S[(g + 8) * 516 + c + 1]);
            o.z = f2h2(S[g * 516 + c + 8],       S[g * 516 + c + 9]);
            o.w = f2h2(S[(g + 8) * 516 + c + 8], S[(g + 8) * 516 + c + 9]);
            size_t di = ((size_t)jm * 64 + ch * 32 + jk_l) * 32 + ln;
            dst[di] = o;
        }
    }
}

// ---------------------------------------------------------------------------
// FP16 GEMM, BK=64 (4 k16), 3-stage cp.async ring (32KB stages).
// Block tile 128x128, 256 thr = 8 warps (4M x 2N), warp = 32x64. 16 chunks.
// Chunk schedule: barrier -> load ks0 fragments -> issue prefetch -> compute.
// MODE: 0 flat fp32; 1 Q frags (*QSCALE); 2 K (fp32 out + K-frags);
//       3 V (fp32 out + V-frags).
// ---------------------------------------------------------------------------
#define GEMM_SMEM 98304

template<int MODE>
__device__ __forceinline__ void gemm_body(const __half* __restrict__ A2h,
                                          const __half* __restrict__ W2h,
                                          float* __restrict__ out_full)
{
    extern __shared__ float dsm[];
    const uint32_t sA = smem_u32(dsm);            // 3 x 16KB A stages
    const uint32_t sB = sA + 3 * 16384;           // 3 x 16KB B stages

    const int tid  = threadIdx.x;
    const int lane = tid & 31;
    const int w    = tid >> 5;
    const int g    = lane >> 2;
    const int tg   = lane & 3;
    const int wm   = w & 3;
    const int wn   = w >> 2;

    const int m0  = blockIdx.y << 7;
    const int n0  = blockIdx.x << 7;
    const int jm0 = blockIdx.y * 8;
    const int jn0 = blockIdx.x * 16;

    const int ajm = tid >> 5, ati = tid & 31;
    const uint4* Ag = (const uint4*)A2h + (size_t)(jm0 + ajm) * 2048;
    const uint2* Bg2 = (const uint2*)W2h;

#pragma unroll
    for (int c = 0; c < 3; c++) {
#pragma unroll
        for (int i = 0; i < 4; i++) {
            cp16(sA + (uint32_t)(c * 16384 + ((ajm * 4 + i) * 32 + ati) * 16),
                 Ag + (c * 4 + i) * 32 + ati);
            int f = tid + i * 256;
            int jn_l = f >> 6, rem = f & 63;
            int jkl = rem >> 4, lp = rem & 15;
            cp16(sB + (uint32_t)(c * 16384 + ((jn_l * 4 + jkl) * 32 + lp * 2) * 8),
                 Bg2 + (size_t)(jn0 + jn_l) * 2048 + (c * 4 + jkl) * 32 + lp * 2);
        }
        CP_COMMIT();
    }

    float acc[2][8][4];
#pragma unroll
    for (int mf = 0; mf < 2; mf++)
#pragma unroll
        for (int nf = 0; nf < 8; nf++)
#pragma unroll
            for (int r = 0; r < 4; r++) acc[mf][nf][r] = 0.0f;

    for (int t = 0; t < 16; t++) {
        if (t < 15) { CP_WAIT(1); } else { CP_WAIT(0); }
        __syncthreads();
        const int st = t % 3;
        const uint4* as4 = (const uint4*)((const char*)dsm + st * 16384);
        const uint2* bs2 = (const uint2*)((const char*)dsm + 3 * 16384 + st * 16384);

        // start the ks=0 dependency chain BEFORE issuing prefetch
        uint4 a0 = as4[((wm * 2 + 0) * 4 + 0) * 32 + lane];
        uint4 a1 = as4[((wm * 2 + 1) * 4 + 0) * 32 + lane];
        uint2 b0 = bs2[((wn * 8 + 0) * 4 + 0) * 32 + lane];

        if (t + 2 < 16) {
            int sn = (t + 2) % 3;
#pragma unroll
            for (int i = 0; i < 4; i++) {
                cp16(sA + (uint32_t)(sn * 16384 + ((ajm * 4 + i) * 32 + ati) * 16),
                     Ag + ((t + 2) * 4 + i) * 32 + ati);
                int f = tid + i * 256;
                int jn_l = f >> 6, rem = f & 63;
                int jkl = rem >> 4, lp = rem & 15;
                cp16(sB + (uint32_t)(sn * 16384 + ((jn_l * 4 + jkl) * 32 + lp * 2) * 8),
                     Bg2 + (size_t)(jn0 + jn_l) * 2048 + ((t + 2) * 4 + jkl) * 32 + lp * 2);
            }
            CP_COMMIT();
        }

        // ks = 0 (pre-loaded fragments)
        mma16(acc[0][0], a0.x, a0.y, a0.z, a0.w, b0.x, b0.y);
        mma16(acc[1][0], a1.x, a1.y, a1.z, a1.w, b0.x, b0.y);
#pragma unroll
        for (int nf = 1; nf < 8; nf++) {
            uint2 b = bs2[((wn * 8 + nf) * 4 + 0) * 32 + lane];
            mma16(acc[0][nf], a0.x, a0.y, a0.z, a0.w, b.x, b.y);
            mma16(acc[1][nf], a1.x, a1.y, a1.z, a1.w, b.x, b.y);
        }
        // ks = 1..3
#pragma unroll
        for (int ks = 1; ks < 4; ks++) {
            uint4 aa0 = as4[((wm * 2 + 0) * 4 + ks) * 32 + lane];
            uint4 aa1 = as4[((wm * 2 + 1) * 4 + ks) * 32 + lane];
#pragma unroll
            for (int nf = 0; nf < 8; nf++) {
                uint2 b = bs2[((wn * 8 + nf) * 4 + ks) * 32 + lane];
                mma16(acc[0][nf], aa0.x, aa0.y, aa0.z, aa0.w, b.x, b.y);
                mma16(acc[1][nf], aa1.x, aa1.y, aa1.z, aa1.w, b.x, b.y);
            }
        }
    }

    if (MODE == 0) {
#pragma unroll
        for (int mf = 0; mf < 2; mf++) {
#pragma unroll
            for (int half = 0; half < 2; half++) {
                int m = m0 + (wm << 5) + (mf << 4) + g + half * 8;
#pragma unroll
                for (int nf = 0; nf < 8; nf++) {
                    int e = n0 + (wn << 6) + (nf << 3) + (tg << 1);
                    float2 val;
                    val.x = acc[mf][nf][half * 2 + 0];
                    val.y = acc[mf][nf][half * 2 + 1];
                    *(float2*)&out_full[(size_t)m * DD + e] = val;
                }
            }
        }
        return;
    }

    // staged epilogue: C tile -> smem fp32 [128][132]
    __syncthreads();
    float* stage = dsm;
#pragma unroll
    for (int mf = 0; mf < 2; mf++) {
#pragma unroll
        for (int half = 0; half < 2; half++) {
            int r = (wm << 5) + (mf << 4) + (half << 3) + g;
#pragma unroll
            for (int nf = 0; nf < 8; nf++) {
                int c = (wn << 6) + (nf << 3) + (tg << 1);
                float2 val;
                val.x = acc[mf][nf][half * 2 + 0];
                val.y = acc[mf][nf][half * 2 + 1];
                *(float2*)&stage[r * 132 + c] = val;
            }
        }
    }
    __syncthreads();

    const int bq = m0 >> 11;
    const int h0 = n0 >> 6;

    if (MODE == 2 || MODE == 3) {
#pragma unroll
        for (int i = 0; i < 16; i++) {
            int f = i * 256 + tid;
            int row = f >> 5, c4 = f & 31;
            float4 v = *(const float4*)&stage[row * 132 + c4 * 4];
            int m = m0 + row;
            int s = m & 2047;
            int e = n0 + c4 * 4;
            int h = e >> 6, dk = e & 63;
            *(float4*)&out_full[((((size_t)bq * HH + h) << 11) + s) * DKK + dk] = v;
        }
    }

    if (MODE == 1) {
        const int jmb = (m0 & 2047) >> 4;
        uint4* dst = (uint4*)g_Qh;
#pragma unroll
        for (int i = 0; i < 8; i++) {
            int f = i * 256 + tid;
            int ln = f & 31, qq = f >> 5;
            int jk = qq & 3, jm_l = (qq >> 2) & 7, hs = (qq >> 5) & 1;
            int g2 = ln >> 2, t2 = ln & 3;
            int r = jm_l * 16 + g2, c = hs * 64 + jk * 16 + 2 * t2;
            uint4 o;
            o.x = f2h2(stage[r * 132 + c] * QSCALE,       stage[r * 132 + c + 1] * QSCALE);
            o.y = f2h2(stage[(r + 8) * 132 + c] * QSCALE, stage[(r + 8) * 132 + c + 1] * QSCALE);
            o.z = f2h2(stage[r * 132 + c + 8] * QSCALE,   stage[r * 132 + c + 9] * QSCALE);
            o.w = f2h2(stage[(r + 8) * 132 + c + 8] * QSCALE,
                       stage[(r + 8) * 132 + c + 9] * QSCALE);
            size_t idx = (((size_t)(bq * HH + h0 + hs) * 128 + jmb + jm_l) * 4 + jk) * 32 + ln;
            dst[idx] = o;
        }
    } else if (MODE == 2) {
        const int kt0 = (m0 & 2047) >> 6;
        uint2* dst = (uint2*)g_rKh;
#pragma unroll
        for (int i = 0; i < 16; i++) {
            int f = i * 256 + tid;
            int ln = f & 31, qq = f >> 5;
            int jk = qq & 3, jn = (qq >> 2) & 7, ktl = (qq >> 5) & 1, hs = qq >> 6;
            int g2 = ln >> 2, t2 = ln & 3;
            int r = ktl * 64 + jn * 8 + g2;
            int c = hs * 64 + jk * 16 + 2 * t2;
            uint2 o;
            o.x = f2h2(stage[r * 132 + c],     stage[r * 132 + c + 1]);
            o.y = f2h2(stage[r * 132 + c + 8], stage[r * 132 + c + 9]);
            size_t idx = ((size_t)(bq * HH + h0 + hs) * 32 + kt0 + ktl) * 1024
                       + (jn * 4 + jk) * 32 + ln;
            dst[idx] = o;
        }
    } else if (MODE == 3) {
        const int kt0 = (m0 & 2047) >> 6;
        uint2* dst = (uint2*)g_rVh;
#pragma unroll
        for (int i = 0; i < 16; i++) {
            int f = i * 256 + tid;
            int ln = f & 31, qq = f >> 5;
            int jk = qq & 3, jn = (qq >> 2) & 7, ktl = (qq >> 5) & 1, hs = qq >> 6;
            int g2 = ln >> 2, t2 = ln & 3;
            int r = ktl * 64 + jk * 16 + 2 * t2;
            int c = hs * 64 + jn * 8 + g2;
            uint2 o;
            o.x = f2h2(stage[r * 132 + c],       stage[(r + 1) * 132 + c]);
            o.y = f2h2(stage[(r + 8) * 132 + c], stage[(r + 9) * 132 + c]);
            size_t idx = ((size_t)(bq * HH + h0 + hs) * 32 + kt0 + ktl) * 1024
                       + (jn * 4 + jk) * 32 + ln;
            dst[idx] = o;
        }
    }
}

__global__ __launch_bounds__(256, 2) void gemm_qkv(
    float* __restrict__ keyh, float* __restrict__ valh)
{
    const int z = blockIdx.z;
    const __half* A2 = g_pA + (size_t)z * MM * DD;
    const __half* W2 = g_rw + (size_t)z * DD * DD;
    if (z == 0)      gemm_body<1>(A2, W2, nullptr);
    else if (z == 1) gemm_body<2>(A2, W2, keyh);
    else             gemm_body<3>(A2, W2, valh);
}

__global__ __launch_bounds__(256, 2) void gemm_out_k(float* __restrict__ O)
{
    gemm_body<0>(g_ctx, g_rw + (size_t)3 * DD * DD, O);
}

// ---------------------------------------------------------------------------
// FP16 causal flash attention (R15 shape — measured best), exp2 softmax,
// 4-slot K/V ring, two 64-key tiles per iteration.
// Grid: (S/128, B*H). Block: 128 thr (4 warps); warp owns 32 query rows.
// ---------------------------------------------------------------------------
#define ATT_SMEM (8 * 8192)

__global__ __launch_bounds__(128, 2) void attn_tc()
{
    extern __shared__ float sm[];
    const uint32_t uKb = smem_u32(sm);          // 4 x 8KB K
    const uint32_t uVb = uKb + 4 * 8192;        // 4 x 8KB V

    const int tid  = threadIdx.x;
    const int lane = tid & 31;
    const int w    = tid >> 5;
    const int g    = lane >> 2;
    const int tg   = lane & 3;
    const int wrow = w << 5;
    const int bxr  = gridDim.x - 1 - blockIdx.x;   // heavy blocks first
    const int bh   = blockIdx.y;

    const int qwarp = bxr * 128 + wrow;

    const __half* Ktiles = g_rKh + (size_t)bh * 32 * 4096;
    const __half* Vtiles = g_rVh + (size_t)bh * 32 * 4096;
    const int ktmax = 2 * bxr + 1;   // odd -> tiles form exact pairs

    // prologue: prefetch tiles 0 and 1 into ring slots 0 and 1
#pragma unroll
    for (int c = 0; c < 2; c++) {
#pragma unroll
        for (int u = 0; u < 4; u++) {
            int f = u * 128 + tid;
            cp16(uKb + (uint32_t)(c * 8192 + f * 16), Ktiles + (size_t)c * 4096 + f * 8);
            cp16(uVb + (uint32_t)(c * 8192 + f * 16), Vtiles + (size_t)c * 4096 + f * 8);
        }
        CP_COMMIT();
    }

    // Q a-fragments straight from global (pre-scaled by QSCALE, fp16)
    uint4 aQ[2][4];
#pragma unroll
    for (int mf = 0; mf < 2; mf++) {
        const uint4* Qf = (const uint4*)g_Qh
                        + ((size_t)bh * 128 + bxr * 8 + w * 2 + mf) * 128;
#pragma unroll
        for (int jk = 0; jk < 4; jk++)
            aQ[mf][jk] = Qf[jk * 32 + lane];
    }

    float accO[2][8][4];
#pragma unroll
    for (int mf = 0; mf < 2; mf++)
#pragma unroll
        for (int nf = 0; nf < 8; nf++)
#pragma unroll
            for (int r = 0; r < 4; r++) accO[mf][nf][r] = 0.0f;
    float m_[2][2] = {{-1e30f, -1e30f}, {-1e30f, -1e30f}};
    float l_[2][2] = {{0.0f, 0.0f}, {0.0f, 0.0f}};

    for (int ktt = 0; ktt <= ktmax; ktt += 2) {
        CP_WAIT(0);        // tiles ktt, ktt+1 resident
        __syncthreads();   // ... and every warp done with slots of ktt-2,ktt-1

        // prefetch next pair into slots (ktt+2)&3, (ktt+3)&3
#pragma unroll
        for (int d = 2; d < 4; d++) {
            int tt = ktt + d;
            if (tt <= ktmax) {
                const int bsel = tt & 3;
                const __half* Kn = Ktiles + (size_t)tt * 4096;
                const __half* Vn = Vtiles + (size_t)tt * 4096;
#pragma unroll
                for (int u = 0; u < 4; u++) {
                    int f = u * 128 + tid;
                    cp16(uKb + (uint32_t)(bsel * 8192 + f * 16), Kn + f * 8);
                    cp16(uVb + (uint32_t)(bsel * 8192 + f * 16), Vn + f * 8);
                }
                CP_COMMIT();
            }
        }

#pragma unroll
        for (int sub = 0; sub < 2; sub++) {
            const int kt = ktt + sub;
            const uint2* Kc = (const uint2*)((const char*)sm + (kt & 3) * 8192);
            const uint2* Vc = (const uint2*)((const char*)sm + 4 * 8192 + (kt & 3) * 8192);

            const bool skip = (kt * 64) > (qwarp + 31);
            if (skip) continue;

            float sacc[2][8][4];
#pragma unroll
            for (int mf = 0; mf < 2; mf++)
#pragma unroll
                for (int nf = 0; nf < 8; nf++)
#pragma unroll
                    for (int r = 0; r < 4; r++) sacc[mf][nf][r] = 0.0f;

            // GEMM1: S2 = (Q*log2e/8) @ K^T
#pragma unroll
            for (int jk = 0; jk < 4; jk++) {
#pragma unroll
                for (int nf = 0; nf < 8; nf++) {
                    uint2 b = Kc[(nf * 4 + jk) * 32 + lane];
                    mma16(sacc[0][nf], aQ[0][jk].x, aQ[0][jk].y, aQ[0][jk].z,
                          aQ[0][jk].w, b.x, b.y);
                    mma16(sacc[1][nf], aQ[1][jk].x, aQ[1][jk].y, aQ[1][jk].z,
                          aQ[1][jk].w, b.x, b.y);
                }
            }

            // causal mask (absolute indices)
            if (kt * 64 + 63 > qwarp) {
                int koff = kt * 64;
#pragma unroll
                for (int mf = 0; mf < 2; mf++) {
                    int r0 = qwarp + (mf << 4) + g, r1 = r0 + 8;
#pragma unroll
                    for (int nf = 0; nf < 8; nf++) {
                        int c0 = koff + nf * 8 + tg * 2, c1 = c0 + 1;
                        if (c0 > r0) sacc[mf][nf][0] = -1e30f;
                        if (c1 > r0) sacc[mf][nf][1] = -1e30f;
                        if (c0 > r1) sacc[mf][nf][2] = -1e30f;
                        if (c1 > r1) sacc[mf][nf][3] = -1e30f;
                    }
                }
            }

            // online softmax in exp2 domain per (mf, row-half)
#pragma unroll
            for (int mf = 0; mf < 2; mf++) {
                float rm0 = -1e30f, rm1 = -1e30f;
#pragma unroll
                for (int nf = 0; nf < 8; nf++) {
                    rm0 = fmaxf(rm0, fmaxf(sacc[mf][nf][0], sacc[mf][nf][1]));
                    rm1 = fmaxf(rm1, fmaxf(sacc[mf][nf][2], sacc[mf][nf][3]));
                }
                rm0 = fmaxf(rm0, __shfl_xor_sync(0xFFFFFFFFu, rm0, 1));
                rm0 = fmaxf(rm0, __shfl_xor_sync(0xFFFFFFFFu, rm0, 2));
                rm1 = fmaxf(rm1, __shfl_xor_sync(0xFFFFFFFFu, rm1, 1));
                rm1 = fmaxf(rm1, __shfl_xor_sync(0xFFFFFFFFu, rm1, 2));
                float mn0 = fmaxf(m_[mf][0], rm0), mn1 = fmaxf(m_[mf][1], rm1);
                float al0 = ex2(m_[mf][0] - mn0), al1 = ex2(m_[mf][1] - mn1);
                float rs0 = 0.0f, rs1 = 0.0f;
#pragma unroll
                for (int nf = 0; nf < 8; nf++) {
                    sacc[mf][nf][0] = ex2(sacc[mf][nf][0] - mn0);
                    sacc[mf][nf][1] = ex2(sacc[mf][nf][1] - mn0);
                    sacc[mf][nf][2] = ex2(sacc[mf][nf][2] - mn1);
                    sacc[mf][nf][3] = ex2(sacc[mf][nf][3] - mn1);
                    rs0 += sacc[mf][nf][0] + sacc[mf][nf][1];
                    rs1 += sacc[mf][nf][2] + sacc[mf][nf][3];
                }
                rs0 += __shfl_xor_sync(0xFFFFFFFFu, rs0, 1);
                rs0 += __shfl_xor_sync(0xFFFFFFFFu, rs0, 2);
                rs1 += __shfl_xor_sync(0xFFFFFFFFu, rs1, 1);
                rs1 += __shfl_xor_sync(0xFFFFFFFFu, rs1, 2);
                l_[mf][0] = l_[mf][0] * al0 + rs0;
                l_[mf][1] = l_[mf][1] * al1 + rs1;
                m_[mf][0] = mn0; m_[mf][1] = mn1;
#pragma unroll
                for (int nf = 0; nf < 8; nf++) {
                    accO[mf][nf][0] *= al0; accO[mf][nf][1] *= al0;
                    accO[mf][nf][2] *= al1; accO[mf][nf][3] *= al1;
                }
            }

            // GEMM2: O += P @ V (register-local P repack)
#pragma unroll
            for (int jk = 0; jk < 4; jk++) {
                uint32_t pa[2][4];
#pragma unroll
                for (int mf = 0; mf < 2; mf++) {
                    pa[mf][0] = f2h2(sacc[mf][2*jk  ][0], sacc[mf][2*jk  ][1]);
                    pa[mf][1] = f2h2(sacc[mf][2*jk  ][2], sacc[mf][2*jk  ][3]);
                    pa[mf][2] = f2h2(sacc[mf][2*jk+1][0], sacc[mf][2*jk+1][1]);
                    pa[mf][3] = f2h2(sacc[mf][2*jk+1][2], sacc[mf][2*jk+1][3]);
                }
#pragma unroll
                for (int nf = 0; nf < 8; nf++) {
                    uint2 b = Vc[(nf * 4 + jk) * 32 + lane];
                    mma16(accO[0][nf], pa[0][0], pa[0][1], pa[0][2], pa[0][3],
                          b.x, b.y);
                    mma16(accO[1][nf], pa[1][0], pa[1][1], pa[1][2], pa[1][3],
                          b.x, b.y);
                }
            }
        }
    }

    // epilogue: normalize, register-local repack to A-frag quads, direct STG
    {
        const int b = bh >> 4;
        const int h = bh & 15;
        uint4* ctx4 = (uint4*)g_ctx;
#pragma unroll
        for (int mf = 0; mf < 2; mf++) {
            float inv0 = 1.0f / l_[mf][0], inv1 = 1.0f / l_[mf][1];
            size_t jm = (size_t)b * 128 + bxr * 8 + w * 2 + mf;
#pragma unroll
            for (int jk = 0; jk < 4; jk++) {
                uint4 o;
                o.x = f2h2(accO[mf][2*jk  ][0] * inv0, accO[mf][2*jk  ][1] * inv0);
                o.y = f2h2(accO[mf][2*jk  ][2] * inv1, accO[mf][2*jk  ][3] * inv1);
                o.z = f2h2(accO[mf][2*jk+1][0] * inv0, accO[mf][2*jk+1][1] * inv0);
                o.w = f2h2(accO[mf][2*jk+1][2] * inv1, accO[mf][2*jk+1][3] * inv1);
                ctx4[(jm * 64 + h * 4 + jk) * 32 + lane] = o;
            }
        }
    }
}

// ---------------------------------------------------------------------------
extern "C" void kernel_launch(void* const* d_in, const int* in_sizes, int n_in,
                              void* d_out, int out_size)
{
    const float* q   = (const float*)d_in[0];
    const float* k   = (const float*)d_in[1];
    const float* v   = (const float*)d_in[2];
    // d_in[3] = mask (causal tril) — computed analytically in-kernel
    const float* w_q = (const float*)d_in[4];
    const float* w_k = (const float*)d_in[5];
    const float* w_v = (const float*)d_in[6];
    const float* w_o = (const float*)d_in[7];

    float* out  = (float*)d_out;
    float* keyh = out + OUT_PLANE;
    float* valh = out + 2 * (size_t)OUT_PLANE;

    static bool configured = false;
    if (!configured) {
        cudaFuncSetAttribute(gemm_qkv, cudaFuncAttributeMaxDynamicSharedMemorySize,
                             GEMM_SMEM);
        cudaFuncSetAttribute(gemm_out_k, cudaFuncAttributeMaxDynamicSharedMemorySize,
                             GEMM_SMEM);
        cudaFuncSetAttribute(attn_tc, cudaFuncAttributeMaxDynamicSharedMemorySize,
                             ATT_SMEM);
        configured = true;
    }

    prep_k<<<3584, 256>>>(q, k, v, w_q, w_k, w_v, w_o);

    dim3 qkvgrid(DD / 128, MM / 128, 3);   // (8, 64, 3)
    gemm_qkv<<<qkvgrid, 256, GEMM_SMEM>>>(keyh, valh);

    dim3 agrid(SS / 128, BB * HH);         // (16, 64)
    attn_tc<<<agrid, 128, ATT_SMEM>>>();

    dim3 ogrid(DD / 128, MM / 128, 1);     // (8, 64)
    gemm_out_k<<<ogrid, 256, GEMM_SMEM>>>(out);
}